// round 7
// baseline (speedup 1.0000x reference)
#include <cuda_runtime.h>
#include <cuda_bf16.h>
#include <cstdint>

#define BB 256
#define PP 196
#define DD 512
#define AA 512
#define MM (BB*PP)   // 50176

// ---------------- scratch (__device__ globals; no allocs) -------------------
__device__ float g_hidden[BB*AA];      // hidden + bv
__device__ float g_sh[BB*AA];          // st@Ws + bs + hidden (pre-tanh)
__device__ float g_z[BB*PP];           // logits
// Wv^T split planes, fragment-packed: plane(0=hi,1=lo), n(512), 32 chunks x 4
// uint2 slots; slot t of chunk c = { bf16pair(k=16c+2t), bf16pair(k=16c+2t+8) }
__device__ uint4 g_WvP4[2*512*64];     // 1MB

// ---------------- helpers ---------------------------------------------------
__device__ __forceinline__ float tanhapx(float x) {
    float y; asm("tanh.approx.f32 %0, %1;" : "=f"(y) : "f"(x)); return y;
}
__device__ __forceinline__ void split2(float2 v, uint32_t& hi, uint32_t& lo) {
    __nv_bfloat16 hx = __float2bfloat16(v.x), hy = __float2bfloat16(v.y);
    __nv_bfloat16 lx = __float2bfloat16(v.x - __bfloat162float(hx));
    __nv_bfloat16 ly = __float2bfloat16(v.y - __bfloat162float(hy));
    hi = (uint32_t)__bfloat16_as_ushort(hx) | ((uint32_t)__bfloat16_as_ushort(hy) << 16);
    lo = (uint32_t)__bfloat16_as_ushort(lx) | ((uint32_t)__bfloat16_as_ushort(ly) << 16);
}
__device__ __forceinline__ void mma16(float* c, const uint32_t* a, const uint32_t* b) {
    asm volatile(
        "mma.sync.aligned.m16n8k16.row.col.f32.bf16.bf16.f32 "
        "{%0,%1,%2,%3}, {%4,%5,%6,%7}, {%8,%9}, {%0,%1,%2,%3};"
        : "+f"(c[0]), "+f"(c[1]), "+f"(c[2]), "+f"(c[3])
        : "r"(a[0]), "r"(a[1]), "r"(a[2]), "r"(a[3]), "r"(b[0]), "r"(b[1]));
}
__device__ __forceinline__ void cpasync16(uint32_t dst, const void* src) {
    asm volatile("cp.async.ca.shared.global [%0], [%1], 16;" :: "r"(dst), "l"(src));
}
#define CP_COMMIT() asm volatile("cp.async.commit_group;" ::: "memory")
#define CP_WAIT0()  asm volatile("cp.async.wait_group 0;" ::: "memory")

// ---------------------------------------------------------------------------
// conv_wv: Wv[k][n] fp32 -> g_WvP4 packed bf16 hi/lo planes [n][k]
// ---------------------------------------------------------------------------
__global__ void __launch_bounds__(256) conv_wv(const float* __restrict__ Wv) {
    __shared__ float s[32][65];
    const int tid = threadIdx.x;
    const int n0  = blockIdx.x * 32;
    uint2* WvP2 = (uint2*)g_WvP4;

    for (int k0 = 0; k0 < DD; k0 += 64) {
        __syncthreads();
        #pragma unroll
        for (int j = 0; j < 8; ++j) {
            const int idx = tid + j*256;
            const int k = idx >> 5, n = idx & 31;
            s[n][k] = Wv[(size_t)(k0 + k)*AA + n0 + n];
        }
        __syncthreads();
        #pragma unroll
        for (int j = 0; j < 4; ++j) {
            const int i = tid + j*256;
            const int plane = i >> 9;
            const int r = i & 511;
            const int n = r >> 4, q = r & 15;
            const int c = q >> 2, t = q & 3;
            const int kl = c*16 + 2*t;
            uint32_t h0, l0, h1, l1;
            split2(make_float2(s[n][kl],   s[n][kl+1]), h0, l0);
            split2(make_float2(s[n][kl+8], s[n][kl+9]), h1, l1);
            uint2 w;
            w.x = plane ? l0 : h0;
            w.y = plane ? l1 : h1;
            WvP2[(size_t)plane*65536 + (size_t)(n0 + n)*128 + (k0/16 + c)*4 + t] = w;
        }
    }
}

// ---------------------------------------------------------------------------
// K1: hidden = dh@Wh + bh (+bv stored);  g_sh = st@Ws + bs + hidden
// ---------------------------------------------------------------------------
__global__ void __launch_bounds__(256) k_prep(
    const float* __restrict__ dh, const float* __restrict__ st,
    const float* __restrict__ Wh, const float* __restrict__ bh,
    const float* __restrict__ Ws, const float* __restrict__ bs,
    const float* __restrict__ bv)
{
    __shared__ float dh_s[4][33], st_s[4][33];
    __shared__ float Wh_s[32][128], Ws_s[32][128];
    const int tid = threadIdx.x;
    const int b0  = blockIdx.y * 4;
    const int a0  = blockIdx.x * 128;
    const int al  = tid & 127;
    const int bl  = (tid >> 7) * 2;

    float acch[2] = {}, accs[2] = {};

    for (int kb = 0; kb < DD; kb += 32) {
        __syncthreads();
        if (tid < 128) {
            const int bb = tid >> 5, kk = tid & 31;
            dh_s[bb][kk] = dh[(b0 + bb)*DD + kb + kk];
            st_s[bb][kk] = st[(b0 + bb)*DD + kb + kk];
        }
        #pragma unroll
        for (int j = 0; j < 4; ++j) {
            const int i  = tid + j*256;
            const int kk = i >> 5, nq = i & 31;
            *(float4*)&Wh_s[kk][nq*4] = *(const float4*)&Wh[(size_t)(kb+kk)*AA + a0 + nq*4];
            *(float4*)&Ws_s[kk][nq*4] = *(const float4*)&Ws[(size_t)(kb+kk)*AA + a0 + nq*4];
        }
        __syncthreads();
        #pragma unroll 8
        for (int k = 0; k < 32; ++k) {
            const float wh = Wh_s[k][al], ws = Ws_s[k][al];
            #pragma unroll
            for (int bi = 0; bi < 2; ++bi) {
                acch[bi] += dh_s[bl+bi][k] * wh;
                accs[bi] += st_s[bl+bi][k] * ws;
            }
        }
    }
    #pragma unroll
    for (int bi = 0; bi < 2; ++bi) {
        const int b = b0 + bl + bi, a = a0 + al;
        const float h = acch[bi] + bh[a];
        g_hidden[(size_t)b*AA + a] = h + bv[a];
        g_sh[(size_t)b*AA + a]     = accs[bi] + bs[a] + h;
    }
}

// ---------------------------------------------------------------------------
// K2: z[m] = bav + sum_a Wav[a]*tanh( enc[m,:]@Wv[:,a] + hidden[b(m),a] )
// bf16 m16n8k16, 3-pass split, double-buffered smem + cp.async pipeline.
// BM=128, BN=128 (nt=4), BK=32; 256 thr / 8 warps (4m x 2n), warp 32x64.
// 2 blocks/SM.
// ---------------------------------------------------------------------------
#define ASTR 12              // uint2 per A row (8 used + 4 pad)
#define BSTR 12              // uint2 per B row
// per-buffer layout (bytes): Ah 0, Al 12288, Bh 24576, Bl 36864; size 49152
#define BUFSZ   49152
#define OFF_H0  98304
#define OFF_H1  98816
#define OFF_WAV 99328
#define OFF_ZS  99840
#define K2_SMEM 100352

__global__ void __launch_bounds__(256, 2) k_zgemm(
    const float* __restrict__ enc, const float* __restrict__ Wav,
    const float* __restrict__ bav)
{
    extern __shared__ unsigned char sm[];
    float* h0s  = (float*)(sm + OFF_H0);
    float* h1s  = (float*)(sm + OFF_H1);
    float* wavs = (float*)(sm + OFF_WAV);
    float* zs   = (float*)(sm + OFF_ZS);
    const uint32_t sbase = (uint32_t)__cvta_generic_to_shared(sm);

    const int tid  = threadIdx.x, lane = tid & 31, wid = tid >> 5;
    const int wm   = wid & 3;           // m-warp 0..3
    const int wn   = wid >> 2;          // n-warp 0..1
    const int gid  = lane >> 2, tig = lane & 3;
    const int m0   = blockIdx.x * 128;
    const int b0   = m0 / PP;
    const int b1   = (m0 + 127) / PP;
    const int bsplit = (b0 + 1) * PP;

    // A staging slots (4 per thread): slot = 128 rows x 8 q
    int sr_[4], sq_[4], skl_[4];
    #pragma unroll
    for (int j = 0; j < 4; ++j) {
        const int slot = tid + j*256;
        sr_[j]  = slot >> 3;
        sq_[j]  = slot & 7;
        skl_[j] = ((sq_[j] >> 2) << 4) + ((sq_[j] & 3) << 1);   // 16c + 2t
    }
    // B staging slots (4 per thread): 2 planes x 128 n x 4 uint4
    int bpl_[4], bn_[4], bs4_[4];
    #pragma unroll
    for (int j = 0; j < 4; ++j) {
        const int i = tid + j*256;
        bpl_[j] = i >> 9;
        bn_[j]  = (i & 511) >> 2;
        bs4_[j] = i & 3;
    }

    if (tid < 128) zs[tid] = 0.f;

    for (int nt = 0; nt < 4; ++nt) {
        const int n0 = nt * 128;
        __syncthreads();   // previous epilogue done with smem
        if (tid < 128) {
            wavs[tid] = Wav[n0 + tid];
            h0s[tid]  = g_hidden[(size_t)b0*AA + n0 + tid];
            h1s[tid]  = g_hidden[(size_t)b1*AA + n0 + tid];
        }

        float acc[2][8][4];
        #pragma unroll
        for (int mi = 0; mi < 2; ++mi)
            #pragma unroll
            for (int ni = 0; ni < 8; ++ni)
                #pragma unroll
                for (int q = 0; q < 4; ++q) acc[mi][ni][q] = 0.f;

        // ---- stage 0 into buffer 0 ----
        {
            float2 pa[4][2];
            #pragma unroll
            for (int j = 0; j < 4; ++j) {
                const float* base = &enc[(size_t)(m0 + sr_[j])*DD + skl_[j]];
                pa[j][0] = *(const float2*)(base);
                pa[j][1] = *(const float2*)(base + 8);
            }
            #pragma unroll
            for (int j = 0; j < 4; ++j) {
                const uint32_t dst = sbase +
                    (bpl_[j] ? 36864u : 24576u) + bn_[j]*96 + bs4_[j]*16;
                cpasync16(dst, &g_WvP4[(size_t)bpl_[j]*32768 +
                                       (size_t)(n0 + bn_[j])*64 + bs4_[j]]);
            }
            CP_COMMIT();
            uint2* Ah = (uint2*)(sm);
            uint2* Al = (uint2*)(sm + 12288);
            #pragma unroll
            for (int j = 0; j < 4; ++j) {
                uint32_t h0w, l0w, h1w, l1w;
                split2(pa[j][0], h0w, l0w);
                split2(pa[j][1], h1w, l1w);
                const int u = sr_[j]*ASTR + sq_[j];
                Ah[u] = make_uint2(h0w, h1w);
                Al[u] = make_uint2(l0w, l1w);
            }
            CP_WAIT0();
        }
        __syncthreads();

        int cur = 0;
        for (int kb = 0; kb < DD; kb += 32) {
            const int has_next = (kb + 32 < DD);
            const int nxt = cur ^ 1;
            float2 pa[4][2];
            if (has_next) {
                #pragma unroll
                for (int j = 0; j < 4; ++j) {
                    const float* base =
                        &enc[(size_t)(m0 + sr_[j])*DD + kb + 32 + skl_[j]];
                    pa[j][0] = *(const float2*)(base);
                    pa[j][1] = *(const float2*)(base + 8);
                }
                const int kc = ((kb + 32) >> 4) * 2;
                #pragma unroll
                for (int j = 0; j < 4; ++j) {
                    const uint32_t dst = sbase + (uint32_t)nxt*BUFSZ +
                        (bpl_[j] ? 36864u : 24576u) + bn_[j]*96 + bs4_[j]*16;
                    cpasync16(dst, &g_WvP4[(size_t)bpl_[j]*32768 +
                                           (size_t)(n0 + bn_[j])*64 + kc + bs4_[j]]);
                }
                CP_COMMIT();
            }

            // ---- compute on buf[cur] ----
            {
                uint2* Ah = (uint2*)(sm + cur*BUFSZ);
                uint2* Al = (uint2*)(sm + cur*BUFSZ + 12288);
                uint2* Bh = (uint2*)(sm + cur*BUFSZ + 24576);
                uint2* Bl = (uint2*)(sm + cur*BUFSZ + 36864);
                #pragma unroll
                for (int c = 0; c < 2; ++c) {
                    uint32_t ah[2][4], alo[2][4];
                    #pragma unroll
                    for (int mi = 0; mi < 2; ++mi) {
                        const int r = wm*32 + mi*16 + gid;
                        const uint2 u0 = Ah[(r    )*ASTR + c*4 + tig];
                        const uint2 u1 = Ah[(r + 8)*ASTR + c*4 + tig];
                        ah[mi][0] = u0.x; ah[mi][1] = u1.x;
                        ah[mi][2] = u0.y; ah[mi][3] = u1.y;
                        const uint2 v0 = Al[(r    )*ASTR + c*4 + tig];
                        const uint2 v1 = Al[(r + 8)*ASTR + c*4 + tig];
                        alo[mi][0] = v0.x; alo[mi][1] = v1.x;
                        alo[mi][2] = v0.y; alo[mi][3] = v1.y;
                    }
                    #pragma unroll
                    for (int ni = 0; ni < 8; ++ni) {
                        const int n = wn*64 + ni*8 + gid;
                        const uint2 ubh = Bh[n*BSTR + c*4 + tig];
                        const uint2 ubl = Bl[n*BSTR + c*4 + tig];
                        const uint32_t bhf[2] = {ubh.x, ubh.y};
                        const uint32_t blf[2] = {ubl.x, ubl.y};
                        #pragma unroll
                        for (int mi = 0; mi < 2; ++mi) {
                            mma16(acc[mi][ni], ah[mi],  bhf);
                            mma16(acc[mi][ni], ah[mi],  blf);
                            mma16(acc[mi][ni], alo[mi], bhf);
                        }
                    }
                }
            }

            if (has_next) {
                uint2* Ah = (uint2*)(sm + nxt*BUFSZ);
                uint2* Al = (uint2*)(sm + nxt*BUFSZ + 12288);
                #pragma unroll
                for (int j = 0; j < 4; ++j) {
                    uint32_t h0w, l0w, h1w, l1w;
                    split2(pa[j][0], h0w, l0w);
                    split2(pa[j][1], h1w, l1w);
                    const int u = sr_[j]*ASTR + sq_[j];
                    Ah[u] = make_uint2(h0w, h1w);
                    Al[u] = make_uint2(l0w, l1w);
                }
                CP_WAIT0();
            }
            __syncthreads();
            cur = nxt;
        }

        // ---- epilogue: tanh(v + hidden) * Wav, row partial sums ----
        float rs[2][2] = {0.f, 0.f, 0.f, 0.f};
        #pragma unroll
        for (int mi = 0; mi < 2; ++mi) {
            const int r_lo = m0 + wm*32 + mi*16 + gid;
            const float* hlo = (r_lo     >= bsplit) ? h1s : h0s;
            const float* hhi = (r_lo + 8 >= bsplit) ? h1s : h0s;
            #pragma unroll
            for (int ni = 0; ni < 8; ++ni) {
                const int c0 = wn*64 + ni*8 + 2*tig;
                const float w0 = wavs[c0], w1 = wavs[c0+1];
                rs[mi][0] += tanhapx(acc[mi][ni][0] + hlo[c0  ]) * w0
                           + tanhapx(acc[mi][ni][1] + hlo[c0+1]) * w1;
                rs[mi][1] += tanhapx(acc[mi][ni][2] + hhi[c0  ]) * w0
                           + tanhapx(acc[mi][ni][3] + hhi[c0+1]) * w1;
            }
        }
        #pragma unroll
        for (int off = 1; off <= 2; off <<= 1) {
            #pragma unroll
            for (int mi = 0; mi < 2; ++mi) {
                rs[mi][0] += __shfl_xor_sync(0xffffffffu, rs[mi][0], off);
                rs[mi][1] += __shfl_xor_sync(0xffffffffu, rs[mi][1], off);
            }
        }
        if (tig == 0) {
            #pragma unroll
            for (int mi = 0; mi < 2; ++mi) {
                atomicAdd(&zs[wm*32 + mi*16 + gid    ], rs[mi][0]);
                atomicAdd(&zs[wm*32 + mi*16 + gid + 8], rs[mi][1]);
            }
        }
    }
    __syncthreads();
    if (tid < 128) g_z[m0 + tid] = zs[tid] + bav[0];
}

// ---------------------------------------------------------------------------
// K3: s_att reduce; softmax; beta; c_t; gated output
// ---------------------------------------------------------------------------
__global__ void __launch_bounds__(256) k_soft(
    const float* __restrict__ enc, const float* __restrict__ st,
    const float* __restrict__ Was, const float* __restrict__ bas,
    float* __restrict__ out)
{
    __shared__ float zsh[PP];
    __shared__ float alpha_sh[PP];
    __shared__ float red[256];
    const int tid = threadIdx.x;
    const int b   = blockIdx.x;
    const int y   = blockIdx.y;

    float sacc = 0.f;
    for (int i = tid; i < AA; i += 256)
        sacc += tanhapx(g_sh[(size_t)b*AA + i]) * Was[i];
    red[tid] = sacc;
    __syncthreads();
    for (int s = 128; s > 0; s >>= 1) {
        if (tid < s) red[tid] += red[tid + s];
        __syncthreads();
    }
    const float sa = red[0] + bas[0];
    __syncthreads();

    if (tid < PP) zsh[tid] = g_z[b*PP + tid];
    __syncthreads();

    red[tid] = (tid < PP) ? zsh[tid] : -1e30f;
    __syncthreads();
    for (int s = 128; s > 0; s >>= 1) {
        if (tid < s) red[tid] = fmaxf(red[tid], red[tid + s]);
        __syncthreads();
    }
    const float m1 = red[0];
    __syncthreads();

    const float e = (tid < PP) ? __expf(zsh[tid] - m1) : 0.f;
    red[tid] = e;
    __syncthreads();
    for (int s = 128; s > 0; s >>= 1) {
        if (tid < s) red[tid] += red[tid + s];
        __syncthreads();
    }
    const float sum1 = red[0];

    if (tid < PP) {
        const float alpha = e / sum1;
        alpha_sh[tid] = alpha;
        if (y == 0) out[BB*DD + b*PP + tid] = alpha;     // alpha_t
    }

    const float m2   = fmaxf(m1, sa);
    const float sum2 = sum1 * __expf(m1 - m2) + __expf(sa - m2);
    const float beta = __expf(sa - m2) / sum2;
    if (y == 0 && tid == 0) out[BB*DD + BB*PP + b] = beta;  // beta_t
    __syncthreads();

    const int d = y*256 + tid;
    const float* ep = enc + (size_t)b*PP*DD + d;
    float acc = 0.f;
    #pragma unroll 8
    for (int p = 0; p < PP; ++p)
        acc += ep[(size_t)p*DD] * alpha_sh[p];

    out[b*DD + d] = beta * st[b*DD + d] + (1.f - beta) * acc;  // c_hat_t
}

// ---------------------------------------------------------------------------
extern "C" void kernel_launch(void* const* d_in, const int* in_sizes, int n_in,
                              void* d_out, int out_size) {
    const float* enc = (const float*)d_in[0];
    const float* dh  = (const float*)d_in[1];
    const float* st  = (const float*)d_in[2];
    const float* Wv  = (const float*)d_in[3];
    const float* bv  = (const float*)d_in[4];
    const float* Wh  = (const float*)d_in[5];
    const float* bh  = (const float*)d_in[6];
    const float* Ws  = (const float*)d_in[7];
    const float* bs  = (const float*)d_in[8];
    const float* Wav = (const float*)d_in[9];
    const float* bav = (const float*)d_in[10];
    const float* Was = (const float*)d_in[11];
    const float* bas = (const float*)d_in[12];
    float* out = (float*)d_out;

    static int smem_set = 0;
    if (!smem_set) {
        cudaFuncSetAttribute(k_zgemm,
            cudaFuncAttributeMaxDynamicSharedMemorySize, K2_SMEM);
        smem_set = 1;
    }

    conv_wv<<<16, 256>>>(Wv);
    k_prep <<<dim3(4, 64), 256>>>(dh, st, Wh, bh, Ws, bs, bv);
    k_zgemm<<<MM/128, 256, K2_SMEM>>>(enc, Wav, bav);
    k_soft <<<dim3(BB, 2), 256>>>(enc, st, Was, bas, out);
}

// round 8
// speedup vs baseline: 1.5374x; 1.5374x over previous
#include <cuda_runtime.h>
#include <cuda_bf16.h>
#include <cstdint>

#define BB 256
#define PP 196
#define DD 512
#define AA 512
#define MM (BB*PP)   // 50176

// ---------------- scratch (__device__ globals; no allocs) -------------------
__device__ float g_hidden[BB*AA];      // hidden + bv
__device__ float g_sh[BB*AA];          // st@Ws + bs + hidden (pre-tanh)
__device__ float g_z[BB*PP];           // logits
// Wv^T split planes, fragment-packed: plane(0=hi,1=lo), n(512), 32 chunks x 4
// uint2 slots; slot t of chunk c = { bf16pair(k=16c+2t), bf16pair(k=16c+2t+8) }
__device__ uint4 g_WvP4[2*512*64];     // 1MB

// ---------------- helpers ---------------------------------------------------
__device__ __forceinline__ float tanhapx(float x) {
    float y; asm("tanh.approx.f32 %0, %1;" : "=f"(y) : "f"(x)); return y;
}
__device__ __forceinline__ void split2(float2 v, uint32_t& hi, uint32_t& lo) {
    __nv_bfloat16 hx = __float2bfloat16(v.x), hy = __float2bfloat16(v.y);
    __nv_bfloat16 lx = __float2bfloat16(v.x - __bfloat162float(hx));
    __nv_bfloat16 ly = __float2bfloat16(v.y - __bfloat162float(hy));
    hi = (uint32_t)__bfloat16_as_ushort(hx) | ((uint32_t)__bfloat16_as_ushort(hy) << 16);
    lo = (uint32_t)__bfloat16_as_ushort(lx) | ((uint32_t)__bfloat16_as_ushort(ly) << 16);
}
__device__ __forceinline__ void mma16(float* c, const uint32_t* a, const uint32_t* b) {
    asm volatile(
        "mma.sync.aligned.m16n8k16.row.col.f32.bf16.bf16.f32 "
        "{%0,%1,%2,%3}, {%4,%5,%6,%7}, {%8,%9}, {%0,%1,%2,%3};"
        : "+f"(c[0]), "+f"(c[1]), "+f"(c[2]), "+f"(c[3])
        : "r"(a[0]), "r"(a[1]), "r"(a[2]), "r"(a[3]), "r"(b[0]), "r"(b[1]));
}

// ---------------------------------------------------------------------------
// conv_wv: Wv[k][n] fp32 -> g_WvP4 packed bf16 hi/lo planes [n][k]
// ---------------------------------------------------------------------------
__global__ void __launch_bounds__(256) conv_wv(const float* __restrict__ Wv) {
    __shared__ float s[32][65];
    const int tid = threadIdx.x;
    const int n0  = blockIdx.x * 32;
    uint2* WvP2 = (uint2*)g_WvP4;

    for (int k0 = 0; k0 < DD; k0 += 64) {
        __syncthreads();
        #pragma unroll
        for (int j = 0; j < 8; ++j) {
            const int idx = tid + j*256;
            const int k = idx >> 5, n = idx & 31;
            s[n][k] = Wv[(size_t)(k0 + k)*AA + n0 + n];
        }
        __syncthreads();
        #pragma unroll
        for (int j = 0; j < 4; ++j) {
            const int i = tid + j*256;
            const int plane = i >> 9;
            const int r = i & 511;
            const int n = r >> 4, q = r & 15;
            const int c = q >> 2, t = q & 3;
            const int kl = c*16 + 2*t;
            uint32_t h0, l0, h1, l1;
            split2(make_float2(s[n][kl],   s[n][kl+1]), h0, l0);
            split2(make_float2(s[n][kl+8], s[n][kl+9]), h1, l1);
            uint2 w;
            w.x = plane ? l0 : h0;
            w.y = plane ? l1 : h1;
            WvP2[(size_t)plane*65536 + (size_t)(n0 + n)*128 + (k0/16 + c)*4 + t] = w;
        }
    }
}

// ---------------------------------------------------------------------------
// K1: hidden = dh@Wh + bh (+bv stored);  g_sh = st@Ws + bs + hidden
// ---------------------------------------------------------------------------
__global__ void __launch_bounds__(256) k_prep(
    const float* __restrict__ dh, const float* __restrict__ st,
    const float* __restrict__ Wh, const float* __restrict__ bh,
    const float* __restrict__ Ws, const float* __restrict__ bs,
    const float* __restrict__ bv)
{
    __shared__ float dh_s[4][33], st_s[4][33];
    __shared__ float Wh_s[32][128], Ws_s[32][128];
    const int tid = threadIdx.x;
    const int b0  = blockIdx.y * 4;
    const int a0  = blockIdx.x * 128;
    const int al  = tid & 127;
    const int bl  = (tid >> 7) * 2;

    float acch[2] = {}, accs[2] = {};

    for (int kb = 0; kb < DD; kb += 32) {
        __syncthreads();
        if (tid < 128) {
            const int bb = tid >> 5, kk = tid & 31;
            dh_s[bb][kk] = dh[(b0 + bb)*DD + kb + kk];
            st_s[bb][kk] = st[(b0 + bb)*DD + kb + kk];
        }
        #pragma unroll
        for (int j = 0; j < 4; ++j) {
            const int i  = tid + j*256;
            const int kk = i >> 5, nq = i & 31;
            *(float4*)&Wh_s[kk][nq*4] = *(const float4*)&Wh[(size_t)(kb+kk)*AA + a0 + nq*4];
            *(float4*)&Ws_s[kk][nq*4] = *(const float4*)&Ws[(size_t)(kb+kk)*AA + a0 + nq*4];
        }
        __syncthreads();
        #pragma unroll 8
        for (int k = 0; k < 32; ++k) {
            const float wh = Wh_s[k][al], ws = Ws_s[k][al];
            #pragma unroll
            for (int bi = 0; bi < 2; ++bi) {
                acch[bi] += dh_s[bl+bi][k] * wh;
                accs[bi] += st_s[bl+bi][k] * ws;
            }
        }
    }
    #pragma unroll
    for (int bi = 0; bi < 2; ++bi) {
        const int b = b0 + bl + bi, a = a0 + al;
        const float h = acch[bi] + bh[a];
        g_hidden[(size_t)b*AA + a] = h + bv[a];
        g_sh[(size_t)b*AA + a]     = accs[bi] + bs[a] + h;
    }
}

// ---------------------------------------------------------------------------
// K2: z[m] = bav + sum_a Wav[a]*tanh( enc[m,:]@Wv[:,a] + hidden[b(m),a] )
// bf16 m16n8k16, 3-pass split. BM=128, BN=256 (nt=2), BK=32;
// 512 thr / 16 warps (4m x 4n), warp 32x64.
// Double-buffered smem, ONE barrier per stage: LDG(next) -> compute(cur)
// -> STS(next) -> sync.
// ---------------------------------------------------------------------------
#define ASTR 12              // uint2 per A row (8 used + 4 pad)
#define BSTR 12              // uint2 per B row
// per-buffer layout (bytes): Ah 0, Al 12288, Bh 24576, Bl 49152; size 73728
#define BUFSZ   73728
#define OFF_H0  147456
#define OFF_H1  148480
#define OFF_WAV 149504
#define OFF_ZS  150528
#define K2_SMEM 151040

__global__ void __launch_bounds__(512, 1) k_zgemm(
    const float* __restrict__ enc, const float* __restrict__ Wav,
    const float* __restrict__ bav)
{
    extern __shared__ unsigned char sm[];
    float* h0s  = (float*)(sm + OFF_H0);
    float* h1s  = (float*)(sm + OFF_H1);
    float* wavs = (float*)(sm + OFF_WAV);
    float* zs   = (float*)(sm + OFF_ZS);

    const int tid  = threadIdx.x, lane = tid & 31, wid = tid >> 5;
    const int wm   = wid & 3;           // m-warp 0..3
    const int wn   = wid >> 2;          // n-warp 0..3
    const int gid  = lane >> 2, tig = lane & 3;
    const int m0   = blockIdx.x * 128;
    const int b0   = m0 / PP;
    const int b1   = (m0 + 127) / PP;
    const int bsplit = (b0 + 1) * PP;

    // A staging slots (2 per thread): 128 rows x 8 q-slots
    int sr_[2], sq_[2], skl_[2];
    #pragma unroll
    for (int j = 0; j < 2; ++j) {
        const int slot = tid + j*512;
        sr_[j]  = slot >> 3;
        sq_[j]  = slot & 7;
        skl_[j] = ((sq_[j] >> 2) << 4) + ((sq_[j] & 3) << 1);   // 16c + 2t
    }
    // B staging slots (4 per thread): 2 planes x 256 n x 4 uint4
    int bpl_[4], bn_[4], bs4_[4];
    #pragma unroll
    for (int j = 0; j < 4; ++j) {
        const int i = tid + j*512;
        bpl_[j] = i >> 10;
        bn_[j]  = (i & 1023) >> 2;
        bs4_[j] = i & 3;
    }

    if (tid < 128) zs[tid] = 0.f;

    for (int nt = 0; nt < 2; ++nt) {
        const int n0 = nt * 256;
        __syncthreads();   // previous epilogue done with smem
        for (int i = tid; i < 256; i += 512) {
            wavs[i] = Wav[n0 + i];
            h0s[i]  = g_hidden[(size_t)b0*AA + n0 + i];
            h1s[i]  = g_hidden[(size_t)b1*AA + n0 + i];
        }

        float acc[2][8][4];
        #pragma unroll
        for (int mi = 0; mi < 2; ++mi)
            #pragma unroll
            for (int ni = 0; ni < 8; ++ni)
                #pragma unroll
                for (int q = 0; q < 4; ++q) acc[mi][ni][q] = 0.f;

        // ---- prologue: stage kb=0 into buffer 0 ----
        {
            float2 pa[2][2];
            uint4  pb[4];
            #pragma unroll
            for (int j = 0; j < 2; ++j) {
                const float* base = &enc[(size_t)(m0 + sr_[j])*DD + skl_[j]];
                pa[j][0] = *(const float2*)(base);
                pa[j][1] = *(const float2*)(base + 8);
            }
            #pragma unroll
            for (int j = 0; j < 4; ++j)
                pb[j] = g_WvP4[(size_t)bpl_[j]*32768 +
                               (size_t)(n0 + bn_[j])*64 + bs4_[j]];
            uint2* Ah = (uint2*)(sm);
            uint2* Al = (uint2*)(sm + 12288);
            #pragma unroll
            for (int j = 0; j < 2; ++j) {
                uint32_t h0w, l0w, h1w, l1w;
                split2(pa[j][0], h0w, l0w);
                split2(pa[j][1], h1w, l1w);
                const int u = sr_[j]*ASTR + sq_[j];
                Ah[u] = make_uint2(h0w, h1w);
                Al[u] = make_uint2(l0w, l1w);
            }
            #pragma unroll
            for (int j = 0; j < 4; ++j) {
                uint4* dst = (uint4*)(sm + (bpl_[j] ? 49152 : 24576));
                dst[bn_[j]*(BSTR/2) + bs4_[j]] = pb[j];
            }
        }
        __syncthreads();

        int cur = 0;
        for (int kb = 0; kb < DD; kb += 32) {
            const int has_next = (kb + 32 < DD);
            const int nxt = cur ^ 1;
            float2 pa[2][2];
            uint4  pb[4];
            if (has_next) {
                #pragma unroll
                for (int j = 0; j < 2; ++j) {
                    const float* base =
                        &enc[(size_t)(m0 + sr_[j])*DD + kb + 32 + skl_[j]];
                    pa[j][0] = *(const float2*)(base);
                    pa[j][1] = *(const float2*)(base + 8);
                }
                const int kc = ((kb + 32) >> 4) * 2;
                #pragma unroll
                for (int j = 0; j < 4; ++j)
                    pb[j] = g_WvP4[(size_t)bpl_[j]*32768 +
                                   (size_t)(n0 + bn_[j])*64 + kc + bs4_[j]];
            }

            // ---- compute on buf[cur] ----
            {
                uint2* Ah = (uint2*)(sm + cur*BUFSZ);
                uint2* Al = (uint2*)(sm + cur*BUFSZ + 12288);
                uint2* Bh = (uint2*)(sm + cur*BUFSZ + 24576);
                uint2* Bl = (uint2*)(sm + cur*BUFSZ + 49152);
                #pragma unroll
                for (int c = 0; c < 2; ++c) {
                    uint32_t ah[2][4], alo[2][4];
                    #pragma unroll
                    for (int mi = 0; mi < 2; ++mi) {
                        const int r = wm*32 + mi*16 + gid;
                        const uint2 u0 = Ah[(r    )*ASTR + c*4 + tig];
                        const uint2 u1 = Ah[(r + 8)*ASTR + c*4 + tig];
                        ah[mi][0] = u0.x; ah[mi][1] = u1.x;
                        ah[mi][2] = u0.y; ah[mi][3] = u1.y;
                        const uint2 v0 = Al[(r    )*ASTR + c*4 + tig];
                        const uint2 v1 = Al[(r + 8)*ASTR + c*4 + tig];
                        alo[mi][0] = v0.x; alo[mi][1] = v1.x;
                        alo[mi][2] = v0.y; alo[mi][3] = v1.y;
                    }
                    #pragma unroll
                    for (int ni = 0; ni < 8; ++ni) {
                        const int n = wn*64 + ni*8 + gid;
                        const uint2 ubh = Bh[n*BSTR + c*4 + tig];
                        const uint2 ubl = Bl[n*BSTR + c*4 + tig];
                        const uint32_t bhf[2] = {ubh.x, ubh.y};
                        const uint32_t blf[2] = {ubl.x, ubl.y};
                        #pragma unroll
                        for (int mi = 0; mi < 2; ++mi) {
                            mma16(acc[mi][ni], ah[mi],  bhf);
                            mma16(acc[mi][ni], ah[mi],  blf);
                            mma16(acc[mi][ni], alo[mi], bhf);
                        }
                    }
                }
            }

            // ---- store next stage into buf[nxt] ----
            if (has_next) {
                uint2* Ah = (uint2*)(sm + nxt*BUFSZ);
                uint2* Al = (uint2*)(sm + nxt*BUFSZ + 12288);
                #pragma unroll
                for (int j = 0; j < 2; ++j) {
                    uint32_t h0w, l0w, h1w, l1w;
                    split2(pa[j][0], h0w, l0w);
                    split2(pa[j][1], h1w, l1w);
                    const int u = sr_[j]*ASTR + sq_[j];
                    Ah[u] = make_uint2(h0w, h1w);
                    Al[u] = make_uint2(l0w, l1w);
                }
                #pragma unroll
                for (int j = 0; j < 4; ++j) {
                    uint4* dst = (uint4*)(sm + nxt*BUFSZ +
                                          (bpl_[j] ? 49152 : 24576));
                    dst[bn_[j]*(BSTR/2) + bs4_[j]] = pb[j];
                }
            }
            __syncthreads();
            cur = nxt;
        }

        // ---- epilogue: tanh(v + hidden) * Wav, row partial sums ----
        float rs[2][2] = {0.f, 0.f, 0.f, 0.f};
        #pragma unroll
        for (int mi = 0; mi < 2; ++mi) {
            const int r_lo = m0 + wm*32 + mi*16 + gid;
            const float* hlo = (r_lo     >= bsplit) ? h1s : h0s;
            const float* hhi = (r_lo + 8 >= bsplit) ? h1s : h0s;
            #pragma unroll
            for (int ni = 0; ni < 8; ++ni) {
                const int c0 = wn*64 + ni*8 + 2*tig;
                const float w0 = wavs[c0], w1 = wavs[c0+1];
                rs[mi][0] += tanhapx(acc[mi][ni][0] + hlo[c0  ]) * w0
                           + tanhapx(acc[mi][ni][1] + hlo[c0+1]) * w1;
                rs[mi][1] += tanhapx(acc[mi][ni][2] + hhi[c0  ]) * w0
                           + tanhapx(acc[mi][ni][3] + hhi[c0+1]) * w1;
            }
        }
        #pragma unroll
        for (int off = 1; off <= 2; off <<= 1) {
            #pragma unroll
            for (int mi = 0; mi < 2; ++mi) {
                rs[mi][0] += __shfl_xor_sync(0xffffffffu, rs[mi][0], off);
                rs[mi][1] += __shfl_xor_sync(0xffffffffu, rs[mi][1], off);
            }
        }
        if (tig == 0) {
            #pragma unroll
            for (int mi = 0; mi < 2; ++mi) {
                atomicAdd(&zs[wm*32 + mi*16 + gid    ], rs[mi][0]);
                atomicAdd(&zs[wm*32 + mi*16 + gid + 8], rs[mi][1]);
            }
        }
    }
    __syncthreads();
    if (tid < 128) g_z[m0 + tid] = zs[tid] + bav[0];
}

// ---------------------------------------------------------------------------
// K3: s_att reduce; softmax; beta; c_t; gated output
// ---------------------------------------------------------------------------
__global__ void __launch_bounds__(256) k_soft(
    const float* __restrict__ enc, const float* __restrict__ st,
    const float* __restrict__ Was, const float* __restrict__ bas,
    float* __restrict__ out)
{
    __shared__ float zsh[PP];
    __shared__ float alpha_sh[PP];
    __shared__ float red[256];
    const int tid = threadIdx.x;
    const int b   = blockIdx.x;
    const int y   = blockIdx.y;

    float sacc = 0.f;
    for (int i = tid; i < AA; i += 256)
        sacc += tanhapx(g_sh[(size_t)b*AA + i]) * Was[i];
    red[tid] = sacc;
    __syncthreads();
    for (int s = 128; s > 0; s >>= 1) {
        if (tid < s) red[tid] += red[tid + s];
        __syncthreads();
    }
    const float sa = red[0] + bas[0];
    __syncthreads();

    if (tid < PP) zsh[tid] = g_z[b*PP + tid];
    __syncthreads();

    red[tid] = (tid < PP) ? zsh[tid] : -1e30f;
    __syncthreads();
    for (int s = 128; s > 0; s >>= 1) {
        if (tid < s) red[tid] = fmaxf(red[tid], red[tid + s]);
        __syncthreads();
    }
    const float m1 = red[0];
    __syncthreads();

    const float e = (tid < PP) ? __expf(zsh[tid] - m1) : 0.f;
    red[tid] = e;
    __syncthreads();
    for (int s = 128; s > 0; s >>= 1) {
        if (tid < s) red[tid] += red[tid + s];
        __syncthreads();
    }
    const float sum1 = red[0];

    if (tid < PP) {
        const float alpha = e / sum1;
        alpha_sh[tid] = alpha;
        if (y == 0) out[BB*DD + b*PP + tid] = alpha;     // alpha_t
    }

    const float m2   = fmaxf(m1, sa);
    const float sum2 = sum1 * __expf(m1 - m2) + __expf(sa - m2);
    const float beta = __expf(sa - m2) / sum2;
    if (y == 0 && tid == 0) out[BB*DD + BB*PP + b] = beta;  // beta_t
    __syncthreads();

    const int d = y*256 + tid;
    const float* ep = enc + (size_t)b*PP*DD + d;
    float acc = 0.f;
    #pragma unroll 8
    for (int p = 0; p < PP; ++p)
        acc += ep[(size_t)p*DD] * alpha_sh[p];

    out[b*DD + d] = beta * st[b*DD + d] + (1.f - beta) * acc;  // c_hat_t
}

// ---------------------------------------------------------------------------
extern "C" void kernel_launch(void* const* d_in, const int* in_sizes, int n_in,
                              void* d_out, int out_size) {
    const float* enc = (const float*)d_in[0];
    const float* dh  = (const float*)d_in[1];
    const float* st  = (const float*)d_in[2];
    const float* Wv  = (const float*)d_in[3];
    const float* bv  = (const float*)d_in[4];
    const float* Wh  = (const float*)d_in[5];
    const float* bh  = (const float*)d_in[6];
    const float* Ws  = (const float*)d_in[7];
    const float* bs  = (const float*)d_in[8];
    const float* Wav = (const float*)d_in[9];
    const float* bav = (const float*)d_in[10];
    const float* Was = (const float*)d_in[11];
    const float* bas = (const float*)d_in[12];
    float* out = (float*)d_out;

    static int smem_set = 0;
    if (!smem_set) {
        cudaFuncSetAttribute(k_zgemm,
            cudaFuncAttributeMaxDynamicSharedMemorySize, K2_SMEM);
        smem_set = 1;
    }

    conv_wv<<<16, 256>>>(Wv);
    k_prep <<<dim3(4, 64), 256>>>(dh, st, Wh, bh, Ws, bs, bv);
    k_zgemm<<<MM/128, 512, K2_SMEM>>>(enc, Wav, bav);
    k_soft <<<dim3(BB, 2), 256>>>(enc, st, Was, bas, out);
}

// round 9
// speedup vs baseline: 1.7445x; 1.1347x over previous
#include <cuda_runtime.h>
#include <cuda_bf16.h>
#include <cstdint>

#define BB 256
#define PP 196
#define DD 512
#define AA 512
#define MM (BB*PP)   // 50176

// ---------------- scratch (__device__ globals; no allocs) -------------------
__device__ float g_hidden[BB*AA];      // hidden + bv
__device__ float g_sh[BB*AA];          // st@Ws + bs + hidden (pre-tanh)
__device__ float g_z[BB*PP];           // logits
// Wv^T split planes, fragment-packed: plane(0=hi,1=lo), n(512), 32 chunks x 4
// uint2 slots; slot t of chunk c = { bf16pair(k=16c+2t), bf16pair(k=16c+2t+8) }
__device__ uint4 g_WvP4[2*512*64];     // 1MB

// ---------------- helpers ---------------------------------------------------
__device__ __forceinline__ float tanhapx(float x) {
    float y; asm("tanh.approx.f32 %0, %1;" : "=f"(y) : "f"(x)); return y;
}
__device__ __forceinline__ void split2(float2 v, uint32_t& hi, uint32_t& lo) {
    __nv_bfloat16 hx = __float2bfloat16(v.x), hy = __float2bfloat16(v.y);
    __nv_bfloat16 lx = __float2bfloat16(v.x - __bfloat162float(hx));
    __nv_bfloat16 ly = __float2bfloat16(v.y - __bfloat162float(hy));
    hi = (uint32_t)__bfloat16_as_ushort(hx) | ((uint32_t)__bfloat16_as_ushort(hy) << 16);
    lo = (uint32_t)__bfloat16_as_ushort(lx) | ((uint32_t)__bfloat16_as_ushort(ly) << 16);
}
__device__ __forceinline__ void mma16(float* c, const uint32_t* a, const uint32_t* b) {
    asm volatile(
        "mma.sync.aligned.m16n8k16.row.col.f32.bf16.bf16.f32 "
        "{%0,%1,%2,%3}, {%4,%5,%6,%7}, {%8,%9}, {%0,%1,%2,%3};"
        : "+f"(c[0]), "+f"(c[1]), "+f"(c[2]), "+f"(c[3])
        : "r"(a[0]), "r"(a[1]), "r"(a[2]), "r"(a[3]), "r"(b[0]), "r"(b[1]));
}
__device__ __forceinline__ void cpasync16(uint32_t dst, const void* src) {
    asm volatile("cp.async.ca.shared.global [%0], [%1], 16;" :: "r"(dst), "l"(src));
}
#define CP_COMMIT() asm volatile("cp.async.commit_group;" ::: "memory")
#define CP_WAIT0()  asm volatile("cp.async.wait_group 0;" ::: "memory")

// ---------------------------------------------------------------------------
// conv_wv: Wv[k][n] fp32 -> g_WvP4 packed bf16 hi/lo planes [n][k]
// ---------------------------------------------------------------------------
__global__ void __launch_bounds__(256) conv_wv(const float* __restrict__ Wv) {
    __shared__ float s[32][65];
    const int tid = threadIdx.x;
    const int n0  = blockIdx.x * 32;
    uint2* WvP2 = (uint2*)g_WvP4;

    for (int k0 = 0; k0 < DD; k0 += 64) {
        __syncthreads();
        #pragma unroll
        for (int j = 0; j < 8; ++j) {
            const int idx = tid + j*256;
            const int k = idx >> 5, n = idx & 31;
            s[n][k] = Wv[(size_t)(k0 + k)*AA + n0 + n];
        }
        __syncthreads();
        #pragma unroll
        for (int j = 0; j < 4; ++j) {
            const int i = tid + j*256;
            const int plane = i >> 9;
            const int r = i & 511;
            const int n = r >> 4, q = r & 15;
            const int c = q >> 2, t = q & 3;
            const int kl = c*16 + 2*t;
            uint32_t h0, l0, h1, l1;
            split2(make_float2(s[n][kl],   s[n][kl+1]), h0, l0);
            split2(make_float2(s[n][kl+8], s[n][kl+9]), h1, l1);
            uint2 w;
            w.x = plane ? l0 : h0;
            w.y = plane ? l1 : h1;
            WvP2[(size_t)plane*65536 + (size_t)(n0 + n)*128 + (k0/16 + c)*4 + t] = w;
        }
    }
}

// ---------------------------------------------------------------------------
// K1: hidden = dh@Wh + bh (+bv stored);  g_sh = st@Ws + bs + hidden
// ---------------------------------------------------------------------------
__global__ void __launch_bounds__(256) k_prep(
    const float* __restrict__ dh, const float* __restrict__ st,
    const float* __restrict__ Wh, const float* __restrict__ bh,
    const float* __restrict__ Ws, const float* __restrict__ bs,
    const float* __restrict__ bv)
{
    __shared__ float dh_s[4][33], st_s[4][33];
    __shared__ float Wh_s[32][128], Ws_s[32][128];
    const int tid = threadIdx.x;
    const int b0  = blockIdx.y * 4;
    const int a0  = blockIdx.x * 128;
    const int al  = tid & 127;
    const int bl  = (tid >> 7) * 2;

    float acch[2] = {}, accs[2] = {};

    for (int kb = 0; kb < DD; kb += 32) {
        __syncthreads();
        if (tid < 128) {
            const int bb = tid >> 5, kk = tid & 31;
            dh_s[bb][kk] = dh[(b0 + bb)*DD + kb + kk];
            st_s[bb][kk] = st[(b0 + bb)*DD + kb + kk];
        }
        #pragma unroll
        for (int j = 0; j < 4; ++j) {
            const int i  = tid + j*256;
            const int kk = i >> 5, nq = i & 31;
            *(float4*)&Wh_s[kk][nq*4] = *(const float4*)&Wh[(size_t)(kb+kk)*AA + a0 + nq*4];
            *(float4*)&Ws_s[kk][nq*4] = *(const float4*)&Ws[(size_t)(kb+kk)*AA + a0 + nq*4];
        }
        __syncthreads();
        #pragma unroll 8
        for (int k = 0; k < 32; ++k) {
            const float wh = Wh_s[k][al], ws = Ws_s[k][al];
            #pragma unroll
            for (int bi = 0; bi < 2; ++bi) {
                acch[bi] += dh_s[bl+bi][k] * wh;
                accs[bi] += st_s[bl+bi][k] * ws;
            }
        }
    }
    #pragma unroll
    for (int bi = 0; bi < 2; ++bi) {
        const int b = b0 + bl + bi, a = a0 + al;
        const float h = acch[bi] + bh[a];
        g_hidden[(size_t)b*AA + a] = h + bv[a];
        g_sh[(size_t)b*AA + a]     = accs[bi] + bs[a] + h;
    }
}

// ---------------------------------------------------------------------------
// K2: z[m] = bav + sum_a Wav[a]*tanh( enc[m,:]@Wv[:,a] + hidden[b(m),a] )
// bf16 m16n8k16, 3-pass split. BM=128, BN=256 (nt=2), BK=32;
// 512 thr / 16 warps (4m x 4n), warp 32x64.
// Double-buffered smem; per stage: cp.async B(next) + LDG A(next) ->
// compute(cur) -> STS A(next) -> cp.wait -> ONE sync. B never touches regs.
// ---------------------------------------------------------------------------
#define ASTR 12              // uint2 per A row (8 used + 4 pad)
#define BSTR 12              // uint2 per B row
// per-buffer layout (bytes): Ah 0, Al 12288, Bh 24576, Bl 49152; size 73728
#define BUFSZ   73728
#define OFF_H0  147456
#define OFF_H1  148480
#define OFF_WAV 149504
#define OFF_ZS  150528
#define K2_SMEM 151040

__global__ void __launch_bounds__(512, 1) k_zgemm(
    const float* __restrict__ enc, const float* __restrict__ Wav,
    const float* __restrict__ bav)
{
    extern __shared__ unsigned char sm[];
    float* h0s  = (float*)(sm + OFF_H0);
    float* h1s  = (float*)(sm + OFF_H1);
    float* wavs = (float*)(sm + OFF_WAV);
    float* zs   = (float*)(sm + OFF_ZS);
    const uint32_t sbase = (uint32_t)__cvta_generic_to_shared(sm);

    const int tid  = threadIdx.x, lane = tid & 31, wid = tid >> 5;
    const int wm   = wid & 3;           // m-warp 0..3
    const int wn   = wid >> 2;          // n-warp 0..3
    const int gid  = lane >> 2, tig = lane & 3;
    const int m0   = blockIdx.x * 128;
    const int b0   = m0 / PP;
    const int b1   = (m0 + 127) / PP;
    const int bsplit = (b0 + 1) * PP;

    // A staging slots (2 per thread): 128 rows x 8 q-slots
    int sr_[2], sq_[2], skl_[2];
    #pragma unroll
    for (int j = 0; j < 2; ++j) {
        const int slot = tid + j*512;
        sr_[j]  = slot >> 3;
        sq_[j]  = slot & 7;
        skl_[j] = ((sq_[j] >> 2) << 4) + ((sq_[j] & 3) << 1);   // 16c + 2t
    }
    // B staging slots (4 per thread): 2 planes x 256 n x 4 uint4 chunks
    int bpl_[4], bn_[4], bs4_[4];
    #pragma unroll
    for (int j = 0; j < 4; ++j) {
        const int i = tid + j*512;
        bpl_[j] = i >> 10;
        bn_[j]  = (i & 1023) >> 2;
        bs4_[j] = i & 3;
    }

    if (tid < 128) zs[tid] = 0.f;

    for (int nt = 0; nt < 2; ++nt) {
        const int n0 = nt * 256;
        __syncthreads();   // previous epilogue done with smem
        for (int i = tid; i < 256; i += 512) {
            wavs[i] = Wav[n0 + i];
            h0s[i]  = g_hidden[(size_t)b0*AA + n0 + i];
            h1s[i]  = g_hidden[(size_t)b1*AA + n0 + i];
        }

        float acc[2][8][4];
        #pragma unroll
        for (int mi = 0; mi < 2; ++mi)
            #pragma unroll
            for (int ni = 0; ni < 8; ++ni)
                #pragma unroll
                for (int q = 0; q < 4; ++q) acc[mi][ni][q] = 0.f;

        // ---- prologue: stage kb=0 into buffer 0 ----
        {
            #pragma unroll
            for (int j = 0; j < 4; ++j) {
                const uint32_t dst = sbase +
                    (bpl_[j] ? 49152u : 24576u) + bn_[j]*96u + bs4_[j]*16u;
                cpasync16(dst, &g_WvP4[(size_t)bpl_[j]*32768 +
                                       (size_t)(n0 + bn_[j])*64 + bs4_[j]]);
            }
            CP_COMMIT();
            float2 pa[2][2];
            #pragma unroll
            for (int j = 0; j < 2; ++j) {
                const float* base = &enc[(size_t)(m0 + sr_[j])*DD + skl_[j]];
                pa[j][0] = *(const float2*)(base);
                pa[j][1] = *(const float2*)(base + 8);
            }
            uint2* Ah = (uint2*)(sm);
            uint2* Al = (uint2*)(sm + 12288);
            #pragma unroll
            for (int j = 0; j < 2; ++j) {
                uint32_t h0w, l0w, h1w, l1w;
                split2(pa[j][0], h0w, l0w);
                split2(pa[j][1], h1w, l1w);
                const int u = sr_[j]*ASTR + sq_[j];
                Ah[u] = make_uint2(h0w, h1w);
                Al[u] = make_uint2(l0w, l1w);
            }
            CP_WAIT0();
        }
        __syncthreads();

        int cur = 0;
        for (int kb = 0; kb < DD; kb += 32) {
            const int has_next = (kb + 32 < DD);
            const int nxt = cur ^ 1;
            float2 pa[2][2];
            if (has_next) {
                // B next stage: cp.async straight into buf[nxt] (no regs)
                const int kc = ((kb + 32) >> 4) * 2;
                #pragma unroll
                for (int j = 0; j < 4; ++j) {
                    const uint32_t dst = sbase + (uint32_t)nxt*BUFSZ +
                        (bpl_[j] ? 49152u : 24576u) + bn_[j]*96u + bs4_[j]*16u;
                    cpasync16(dst, &g_WvP4[(size_t)bpl_[j]*32768 +
                                           (size_t)(n0 + bn_[j])*64 + kc + bs4_[j]]);
                }
                CP_COMMIT();
                // A next stage: prefetch to regs (8 regs)
                #pragma unroll
                for (int j = 0; j < 2; ++j) {
                    const float* base =
                        &enc[(size_t)(m0 + sr_[j])*DD + kb + 32 + skl_[j]];
                    pa[j][0] = *(const float2*)(base);
                    pa[j][1] = *(const float2*)(base + 8);
                }
            }

            // ---- compute on buf[cur] ----
            {
                uint2* Ah = (uint2*)(sm + cur*BUFSZ);
                uint2* Al = (uint2*)(sm + cur*BUFSZ + 12288);
                uint2* Bh = (uint2*)(sm + cur*BUFSZ + 24576);
                uint2* Bl = (uint2*)(sm + cur*BUFSZ + 49152);
                #pragma unroll
                for (int c = 0; c < 2; ++c) {
                    uint32_t ah[2][4], alo[2][4];
                    #pragma unroll
                    for (int mi = 0; mi < 2; ++mi) {
                        const int r = wm*32 + mi*16 + gid;
                        const uint2 u0 = Ah[(r    )*ASTR + c*4 + tig];
                        const uint2 u1 = Ah[(r + 8)*ASTR + c*4 + tig];
                        ah[mi][0] = u0.x; ah[mi][1] = u1.x;
                        ah[mi][2] = u0.y; ah[mi][3] = u1.y;
                        const uint2 v0 = Al[(r    )*ASTR + c*4 + tig];
                        const uint2 v1 = Al[(r + 8)*ASTR + c*4 + tig];
                        alo[mi][0] = v0.x; alo[mi][1] = v1.x;
                        alo[mi][2] = v0.y; alo[mi][3] = v1.y;
                    }
                    #pragma unroll
                    for (int ni = 0; ni < 8; ++ni) {
                        const int n = wn*64 + ni*8 + gid;
                        const uint2 ubh = Bh[n*BSTR + c*4 + tig];
                        const uint2 ubl = Bl[n*BSTR + c*4 + tig];
                        const uint32_t bhf[2] = {ubh.x, ubh.y};
                        const uint32_t blf[2] = {ubl.x, ubl.y};
                        #pragma unroll
                        for (int mi = 0; mi < 2; ++mi) {
                            mma16(acc[mi][ni], ah[mi],  bhf);
                            mma16(acc[mi][ni], ah[mi],  blf);
                            mma16(acc[mi][ni], alo[mi], bhf);
                        }
                    }
                }
            }

            // ---- store next A stage into buf[nxt]; wait for B cp.async ----
            if (has_next) {
                uint2* Ah = (uint2*)(sm + nxt*BUFSZ);
                uint2* Al = (uint2*)(sm + nxt*BUFSZ + 12288);
                #pragma unroll
                for (int j = 0; j < 2; ++j) {
                    uint32_t h0w, l0w, h1w, l1w;
                    split2(pa[j][0], h0w, l0w);
                    split2(pa[j][1], h1w, l1w);
                    const int u = sr_[j]*ASTR + sq_[j];
                    Ah[u] = make_uint2(h0w, h1w);
                    Al[u] = make_uint2(l0w, l1w);
                }
                CP_WAIT0();
            }
            __syncthreads();
            cur = nxt;
        }

        // ---- epilogue: tanh(v + hidden) * Wav, row partial sums ----
        float rs[2][2] = {0.f, 0.f, 0.f, 0.f};
        #pragma unroll
        for (int mi = 0; mi < 2; ++mi) {
            const int r_lo = m0 + wm*32 + mi*16 + gid;
            const float* hlo = (r_lo     >= bsplit) ? h1s : h0s;
            const float* hhi = (r_lo + 8 >= bsplit) ? h1s : h0s;
            #pragma unroll
            for (int ni = 0; ni < 8; ++ni) {
                const int c0 = wn*64 + ni*8 + 2*tig;
                const float w0 = wavs[c0], w1 = wavs[c0+1];
                rs[mi][0] += tanhapx(acc[mi][ni][0] + hlo[c0  ]) * w0
                           + tanhapx(acc[mi][ni][1] + hlo[c0+1]) * w1;
                rs[mi][1] += tanhapx(acc[mi][ni][2] + hhi[c0  ]) * w0
                           + tanhapx(acc[mi][ni][3] + hhi[c0+1]) * w1;
            }
        }
        #pragma unroll
        for (int off = 1; off <= 2; off <<= 1) {
            #pragma unroll
            for (int mi = 0; mi < 2; ++mi) {
                rs[mi][0] += __shfl_xor_sync(0xffffffffu, rs[mi][0], off);
                rs[mi][1] += __shfl_xor_sync(0xffffffffu, rs[mi][1], off);
            }
        }
        if (tig == 0) {
            #pragma unroll
            for (int mi = 0; mi < 2; ++mi) {
                atomicAdd(&zs[wm*32 + mi*16 + gid    ], rs[mi][0]);
                atomicAdd(&zs[wm*32 + mi*16 + gid + 8], rs[mi][1]);
            }
        }
    }
    __syncthreads();
    if (tid < 128) g_z[m0 + tid] = zs[tid] + bav[0];
}

// ---------------------------------------------------------------------------
// K3: s_att reduce; softmax; beta; c_t; gated output
// ---------------------------------------------------------------------------
__global__ void __launch_bounds__(256) k_soft(
    const float* __restrict__ enc, const float* __restrict__ st,
    const float* __restrict__ Was, const float* __restrict__ bas,
    float* __restrict__ out)
{
    __shared__ float zsh[PP];
    __shared__ float alpha_sh[PP];
    __shared__ float red[256];
    const int tid = threadIdx.x;
    const int b   = blockIdx.x;
    const int y   = blockIdx.y;

    float sacc = 0.f;
    for (int i = tid; i < AA; i += 256)
        sacc += tanhapx(g_sh[(size_t)b*AA + i]) * Was[i];
    red[tid] = sacc;
    __syncthreads();
    for (int s = 128; s > 0; s >>= 1) {
        if (tid < s) red[tid] += red[tid + s];
        __syncthreads();
    }
    const float sa = red[0] + bas[0];
    __syncthreads();

    if (tid < PP) zsh[tid] = g_z[b*PP + tid];
    __syncthreads();

    red[tid] = (tid < PP) ? zsh[tid] : -1e30f;
    __syncthreads();
    for (int s = 128; s > 0; s >>= 1) {
        if (tid < s) red[tid] = fmaxf(red[tid], red[tid + s]);
        __syncthreads();
    }
    const float m1 = red[0];
    __syncthreads();

    const float e = (tid < PP) ? __expf(zsh[tid] - m1) : 0.f;
    red[tid] = e;
    __syncthreads();
    for (int s = 128; s > 0; s >>= 1) {
        if (tid < s) red[tid] += red[tid + s];
        __syncthreads();
    }
    const float sum1 = red[0];

    if (tid < PP) {
        const float alpha = e / sum1;
        alpha_sh[tid] = alpha;
        if (y == 0) out[BB*DD + b*PP + tid] = alpha;     // alpha_t
    }

    const float m2   = fmaxf(m1, sa);
    const float sum2 = sum1 * __expf(m1 - m2) + __expf(sa - m2);
    const float beta = __expf(sa - m2) / sum2;
    if (y == 0 && tid == 0) out[BB*DD + BB*PP + b] = beta;  // beta_t
    __syncthreads();

    const int d = y*256 + tid;
    const float* ep = enc + (size_t)b*PP*DD + d;
    float acc = 0.f;
    #pragma unroll 8
    for (int p = 0; p < PP; ++p)
        acc += ep[(size_t)p*DD] * alpha_sh[p];

    out[b*DD + d] = beta * st[b*DD + d] + (1.f - beta) * acc;  // c_hat_t
}

// ---------------------------------------------------------------------------
extern "C" void kernel_launch(void* const* d_in, const int* in_sizes, int n_in,
                              void* d_out, int out_size) {
    const float* enc = (const float*)d_in[0];
    const float* dh  = (const float*)d_in[1];
    const float* st  = (const float*)d_in[2];
    const float* Wv  = (const float*)d_in[3];
    const float* bv  = (const float*)d_in[4];
    const float* Wh  = (const float*)d_in[5];
    const float* bh  = (const float*)d_in[6];
    const float* Ws  = (const float*)d_in[7];
    const float* bs  = (const float*)d_in[8];
    const float* Wav = (const float*)d_in[9];
    const float* bav = (const float*)d_in[10];
    const float* Was = (const float*)d_in[11];
    const float* bas = (const float*)d_in[12];
    float* out = (float*)d_out;

    static int smem_set = 0;
    if (!smem_set) {
        cudaFuncSetAttribute(k_zgemm,
            cudaFuncAttributeMaxDynamicSharedMemorySize, K2_SMEM);
        smem_set = 1;
    }

    conv_wv<<<16, 256>>>(Wv);
    k_prep <<<dim3(4, 64), 256>>>(dh, st, Wh, bh, Ws, bs, bv);
    k_zgemm<<<MM/128, 512, K2_SMEM>>>(enc, Wav, bav);
    k_soft <<<dim3(BB, 2), 256>>>(enc, st, Was, bas, out);
}